// round 15
// baseline (speedup 1.0000x reference)
#include <cuda_runtime.h>
#include <cstdint>

#define BATCH   8192
#define CLASSES 10000
#define C4      2500                    // float4 per row
#define THREADS 1024
#define MAXGRID 160
#define NREP    8
#define NBUF    4
#define TILE_BYTES (CLASSES * 4)        // 40000 B: one row per tile
#define SMEM_DYN   (NBUF * TILE_BYTES)  // 160000 B raw ring

// zero-initialized at module load; k_fin consume-and-clears after each use,
// so the invariant "zeroed at kernel_launch entry" holds on every replay.
__device__ float g_rep[NREP][CLASSES];
__device__ float g_counts[CLASSES];

// ---------------------------------------------------------------- helpers
__device__ __forceinline__ uint32_t s2u(const void* p) {
    uint32_t a;
    asm("{ .reg .u64 t; cvta.to.shared.u64 t, %1; cvt.u32.u64 %0, t; }"
        : "=r"(a) : "l"(p));
    return a;
}

__device__ __forceinline__ void mbar_init(uint32_t mb, uint32_t cnt) {
    asm volatile("mbarrier.init.shared.b64 [%0], %1;" :: "r"(mb), "r"(cnt) : "memory");
}

__device__ __forceinline__ void mbar_wait(uint32_t mb, uint32_t parity) {
    asm volatile(
        "{\n\t"
        ".reg .pred P;\n\t"
        "WL_%=: mbarrier.try_wait.parity.acquire.cta.shared::cta.b64 P, [%0], %1, 0x989680;\n\t"
        "@P bra.uni WD_%=;\n\t"
        "bra.uni WL_%=;\n\t"
        "WD_%=:\n\t"
        "}" :: "r"(mb), "r"(parity) : "memory");
}

// one elected thread: expect_tx + one bulk-async 40000B copy (one row)
__device__ __forceinline__ void issue_tile(const float* __restrict__ x,
                                           char* dyn, uint32_t mb,
                                           int buf, long long tile) {
    asm volatile("mbarrier.arrive.expect_tx.shared.b64 _, [%0], %1;"
                 :: "r"(mb), "r"((uint32_t)TILE_BYTES) : "memory");
    const char* src = (const char*)x + (size_t)tile * TILE_BYTES;
    uint32_t dst = s2u(dyn + buf * TILE_BYTES);
    asm volatile(
        "cp.async.bulk.shared::cta.global.mbarrier::complete_tx::bytes "
        "[%0], [%1], %2, [%3];"
        :: "r"(dst), "l"(src), "r"((uint32_t)TILE_BYTES), "r"(mb) : "memory");
}

// ---------------------------------------------------------------- persistent main
// 1 CTA/SM, 1024 threads, 4-deep cp.async.bulk ring, ONE ROW per tile.
// Thread t owns float4 class-groups {t, t+1024, t+2048} for every row: exp
// values live in registers for both the rowsum and the accumulation — no
// fp16 stage, no SMEM RMW, full fp32. 2 barriers per tile. Histogram runs in
// blocks 0..7 overlapped with the mainloop. Flush = red.global.add.v4 into
// one of 8 replica arrays.
__global__ __launch_bounds__(THREADS, 1) void k_main(const float* __restrict__ x,
                                                     const int* __restrict__ tgt,
                                                     float* __restrict__ out,
                                                     int grid) {
    extern __shared__ char dyn[];
    __shared__ float    wred[32];
    __shared__ float    s_inv;
    __shared__ uint64_t mbar[NBUF];

    const int tid = threadIdx.x;
    const int bid = blockIdx.x;
    if (bid == 0 && tid == 0) out[0] = 0.0f;   // ordered before k_fin (stream)

    uint32_t mb[NBUF];
    #pragma unroll
    for (int b = 0; b < NBUF; b++) mb[b] = s2u(&mbar[b]);
    if (tid == 0) {
        #pragma unroll
        for (int b = 0; b < NBUF; b++) mbar_init(mb[b], 1);
    }
    __syncthreads();

    const int n = (BATCH - 1 - bid) / grid + 1;   // rows owned by this CTA
    if (tid == 0) {
        #pragma unroll
        for (int b = 0; b < NBUF; b++)
            if (b < n) issue_tile(x, dyn, mb[b], b, bid + (long long)b * grid);
    }

    // histogram side-job (blocks 0..7, 1024 targets each), overlapped with
    // the TMA-fed mainloop. Dtype-robust: detect int64-LE (odd int32 words
    // zero for values < 2^32) vs int32.
    if (bid < 8) {
        bool is64 = true;
        #pragma unroll
        for (int j = 1; j < 16; j += 2) is64 = is64 && (tgt[j] == 0);
        int i = bid * 1024 + tid;
        int t = is64 ? tgt[2 * i] : tgt[i];
        if (t >= 0 && t < CLASSES) atomicAdd(&g_counts[t], 1.0f);
    }

    float acc[3][4];
    #pragma unroll
    for (int k = 0; k < 3; k++)
        acc[k][0] = acc[k][1] = acc[k][2] = acc[k][3] = 0.0f;

    for (int i = 0; i < n; i++) {
        const int buf = i & (NBUF - 1);
        mbar_wait(mb[buf], (i >> 2) & 1);

        const float4* raw4 = reinterpret_cast<const float4*>(dyn + buf * TILE_BYTES);

        // ---- exp + row sum, exps kept in registers
        float e[3][4];
        float s = 0.0f;
        #pragma unroll
        for (int k = 0; k < 3; k++) {
            int idx = tid + 1024 * k;
            if (k < 2 || idx < C4) {
                float4 v = raw4[idx];
                e[k][0] = __expf(v.x); e[k][1] = __expf(v.y);
                e[k][2] = __expf(v.z); e[k][3] = __expf(v.w);
                s += (e[k][0] + e[k][1]) + (e[k][2] + e[k][3]);
            }
        }
        #pragma unroll
        for (int o = 16; o; o >>= 1) s += __shfl_down_sync(0xffffffffu, s, o);
        if ((tid & 31) == 0) wred[tid >> 5] = s;
        __syncthreads();                     // raw reads + wred stores done

        // re-arm this buffer for tile i+NBUF while everyone else proceeds
        if (tid == 0 && i + NBUF < n)
            issue_tile(x, dyn, mb[buf], buf, bid + (long long)(i + NBUF) * grid);

        if (tid < 32) {
            float t = wred[tid];
            #pragma unroll
            for (int o = 16; o; o >>= 1) t += __shfl_down_sync(0xffffffffu, t, o);
            if (tid == 0) s_inv = 1.0f / t;
        }
        __syncthreads();
        const float inv = s_inv;

        // ---- accumulate: same thread<->class map, straight from registers
        #pragma unroll
        for (int k = 0; k < 3; k++) {
            int idx = tid + 1024 * k;
            if (k < 2 || idx < C4) {
                acc[k][0] += e[k][0] * inv;
                acc[k][1] += e[k][1] * inv;
                acc[k][2] += e[k][2] * inv;
                acc[k][3] += e[k][3] * inv;
            }
        }
        // no trailing barrier: wred(i+1) writes happen only after bar2(i)
        // (program order), and s_inv(i+1) is written only after bar1(i+1).
    }

    // flush: vector-RED into one of 8 replica arrays (16B-aligned rows),
    // fire-and-forget (kernel boundary provides global visibility for k_fin).
    float* rep = g_rep[bid & (NREP - 1)];
    #pragma unroll
    for (int k = 0; k < 3; k++) {
        int idx = tid + 1024 * k;
        if (k < 2 || idx < C4) {
            float* p = rep + 4 * idx;
            asm volatile("red.global.add.v4.f32 [%0], {%1, %2, %3, %4};"
                         :: "l"(p), "f"(acc[k][0]), "f"(acc[k][1]),
                            "f"(acc[k][2]), "f"(acc[k][3]) : "memory");
        }
    }
}

// ---------------------------------------------------------------- tiny epilogue
// 40 blocks x 256 threads: <=1 class per thread. Read 8 L2-hot replicas +
// count, |conf - count|/B, consume-and-clear state for the next replay,
// block-reduce, one atomicAdd per block.
__global__ __launch_bounds__(256) void k_fin(float* __restrict__ out) {
    const int tid = threadIdx.x;
    const int c   = blockIdx.x * 256 + tid;

    float s = 0.0f;
    if (c < CLASSES) {
        float v = 0.0f;
        #pragma unroll
        for (int p = 0; p < NREP; p++) { v += g_rep[p][c]; g_rep[p][c] = 0.0f; }
        v -= g_counts[c];
        g_counts[c] = 0.0f;                  // clear for next replay
        s = fabsf(v) * (1.0f / (float)BATCH);
    }

    __shared__ float sm[8];
    #pragma unroll
    for (int o = 16; o; o >>= 1) s += __shfl_down_sync(0xffffffffu, s, o);
    if ((tid & 31) == 0) sm[tid >> 5] = s;
    __syncthreads();
    if (tid < 8) {
        float t = sm[tid];
        t += __shfl_down_sync(0xffu, t, 4);
        t += __shfl_down_sync(0xffu, t, 2);
        t += __shfl_down_sync(0xffu, t, 1);
        if (tid == 0) atomicAdd(out, t / (float)CLASSES);
    }
}

// ---------------------------------------------------------------- launch
extern "C" void kernel_launch(void* const* d_in, const int* in_sizes, int n_in,
                              void* d_out, int out_size) {
    const float* x   = (const float*)d_in[0];   // [8192, 10000] fp32
    const int*   tgt = (const int*)d_in[1];     // [8192] int32 or int64 (detected)
    float*       out = (float*)d_out;

    int sms = 0;
    cudaDeviceGetAttribute(&sms, cudaDevAttrMultiProcessorCount, 0);
    int grid = sms;                              // 1 persistent CTA per SM
    if (grid < 9)       grid = 9;                // histogram needs blocks 0..7
    if (grid > MAXGRID) grid = MAXGRID;

    cudaFuncSetAttribute(k_main, cudaFuncAttributeMaxDynamicSharedMemorySize,
                         SMEM_DYN);

    k_main<<<grid, THREADS, SMEM_DYN>>>(x, tgt, out, grid);
    k_fin<<<(CLASSES + 255) / 256, 256>>>(out);   // 40 blocks
}

// round 16
// speedup vs baseline: 1.3249x; 1.3249x over previous
#include <cuda_runtime.h>
#include <cstdint>

#define BATCH   8192
#define CLASSES 10000
#define C4      2500                    // float4 per row
#define THREADS 1024
#define MAXGRID 160
#define NREP    8
#define NBUF    4
#define TILE_BYTES (CLASSES * 4)        // 40000 B: one row per tile
#define CHUNK      10000                // 4 bulk copies per tile -> 16 in flight
#define SMEM_DYN   (NBUF * TILE_BYTES)  // 160000 B raw ring

// zero-initialized at module load; k_fin consume-and-clears after each use,
// so the invariant "zeroed at kernel_launch entry" holds on every replay.
__device__ float g_rep[NREP][CLASSES];
__device__ float g_counts[CLASSES];

// ---------------------------------------------------------------- helpers
__device__ __forceinline__ uint32_t s2u(const void* p) {
    uint32_t a;
    asm("{ .reg .u64 t; cvta.to.shared.u64 t, %1; cvt.u32.u64 %0, t; }"
        : "=r"(a) : "l"(p));
    return a;
}

__device__ __forceinline__ void mbar_init(uint32_t mb, uint32_t cnt) {
    asm volatile("mbarrier.init.shared.b64 [%0], %1;" :: "r"(mb), "r"(cnt) : "memory");
}

__device__ __forceinline__ void mbar_wait(uint32_t mb, uint32_t parity) {
    asm volatile(
        "{\n\t"
        ".reg .pred P;\n\t"
        "WL_%=: mbarrier.try_wait.parity.acquire.cta.shared::cta.b64 P, [%0], %1, 0x989680;\n\t"
        "@P bra.uni WD_%=;\n\t"
        "bra.uni WL_%=;\n\t"
        "WD_%=:\n\t"
        "}" :: "r"(mb), "r"(parity) : "memory");
}

// one elected thread: expect_tx + FOUR bulk-async 10000B copies (one row).
// Splitting matters: per-UBLKCP service rate is bounded, so aggregate BW
// scales with concurrent copies (R14: 8 in flight @ 6.5TB/s; R15: 4 in
// flight @ ~3.2TB/s). 4 chunks x NBUF=4 -> 16 in flight.
__device__ __forceinline__ void issue_tile(const float* __restrict__ x,
                                           char* dyn, uint32_t mb,
                                           int buf, long long tile) {
    asm volatile("mbarrier.arrive.expect_tx.shared.b64 _, [%0], %1;"
                 :: "r"(mb), "r"((uint32_t)TILE_BYTES) : "memory");
    const char* src = (const char*)x + (size_t)tile * TILE_BYTES;
    uint32_t dst = s2u(dyn + buf * TILE_BYTES);
    #pragma unroll
    for (int c = 0; c < 4; c++) {
        asm volatile(
            "cp.async.bulk.shared::cta.global.mbarrier::complete_tx::bytes "
            "[%0], [%1], %2, [%3];"
            :: "r"(dst + c * CHUNK), "l"(src + (size_t)c * CHUNK),
               "r"((uint32_t)CHUNK), "r"(mb) : "memory");
    }
}

// ---------------------------------------------------------------- persistent main
// 1 CTA/SM, 1024 threads, 4-deep cp.async.bulk ring, ONE ROW per tile.
// Thread t owns float4 class-groups {t, t+1024, t+2048} for every row: exp
// values live in registers for both the rowsum and the accumulation — no
// fp16 stage, no SMEM RMW, full fp32. 2 barriers per tile. Histogram runs in
// blocks 0..7 overlapped with the mainloop. Flush = red.global.add.v4 into
// one of 8 replica arrays.
__global__ __launch_bounds__(THREADS, 1) void k_main(const float* __restrict__ x,
                                                     const int* __restrict__ tgt,
                                                     float* __restrict__ out,
                                                     int grid) {
    extern __shared__ char dyn[];
    __shared__ float    wred[32];
    __shared__ float    s_inv;
    __shared__ uint64_t mbar[NBUF];

    const int tid = threadIdx.x;
    const int bid = blockIdx.x;
    if (bid == 0 && tid == 0) out[0] = 0.0f;   // ordered before k_fin (stream)

    uint32_t mb[NBUF];
    #pragma unroll
    for (int b = 0; b < NBUF; b++) mb[b] = s2u(&mbar[b]);
    if (tid == 0) {
        #pragma unroll
        for (int b = 0; b < NBUF; b++) mbar_init(mb[b], 1);
    }
    __syncthreads();

    const int n = (BATCH - 1 - bid) / grid + 1;   // rows owned by this CTA
    if (tid == 0) {
        #pragma unroll
        for (int b = 0; b < NBUF; b++)
            if (b < n) issue_tile(x, dyn, mb[b], b, bid + (long long)b * grid);
    }

    // histogram side-job (blocks 0..7, 1024 targets each), overlapped with
    // the TMA-fed mainloop. Dtype-robust: detect int64-LE (odd int32 words
    // zero for values < 2^32) vs int32.
    if (bid < 8) {
        bool is64 = true;
        #pragma unroll
        for (int j = 1; j < 16; j += 2) is64 = is64 && (tgt[j] == 0);
        int i = bid * 1024 + tid;
        int t = is64 ? tgt[2 * i] : tgt[i];
        if (t >= 0 && t < CLASSES) atomicAdd(&g_counts[t], 1.0f);
    }

    float acc[3][4];
    #pragma unroll
    for (int k = 0; k < 3; k++)
        acc[k][0] = acc[k][1] = acc[k][2] = acc[k][3] = 0.0f;

    for (int i = 0; i < n; i++) {
        const int buf = i & (NBUF - 1);
        mbar_wait(mb[buf], (i >> 2) & 1);

        const float4* raw4 = reinterpret_cast<const float4*>(dyn + buf * TILE_BYTES);

        // ---- exp + row sum, exps kept in registers
        float e[3][4];
        float s = 0.0f;
        #pragma unroll
        for (int k = 0; k < 3; k++) {
            int idx = tid + 1024 * k;
            if (k < 2 || idx < C4) {
                float4 v = raw4[idx];
                e[k][0] = __expf(v.x); e[k][1] = __expf(v.y);
                e[k][2] = __expf(v.z); e[k][3] = __expf(v.w);
                s += (e[k][0] + e[k][1]) + (e[k][2] + e[k][3]);
            }
        }
        #pragma unroll
        for (int o = 16; o; o >>= 1) s += __shfl_down_sync(0xffffffffu, s, o);
        if ((tid & 31) == 0) wred[tid >> 5] = s;
        __syncthreads();                     // raw reads + wred stores done

        // re-arm this buffer for tile i+NBUF while everyone else proceeds
        if (tid == 0 && i + NBUF < n)
            issue_tile(x, dyn, mb[buf], buf, bid + (long long)(i + NBUF) * grid);

        if (tid < 32) {
            float t = wred[tid];
            #pragma unroll
            for (int o = 16; o; o >>= 1) t += __shfl_down_sync(0xffffffffu, t, o);
            if (tid == 0) s_inv = 1.0f / t;
        }
        __syncthreads();
        const float inv = s_inv;

        // ---- accumulate: same thread<->class map, straight from registers
        #pragma unroll
        for (int k = 0; k < 3; k++) {
            int idx = tid + 1024 * k;
            if (k < 2 || idx < C4) {
                acc[k][0] += e[k][0] * inv;
                acc[k][1] += e[k][1] * inv;
                acc[k][2] += e[k][2] * inv;
                acc[k][3] += e[k][3] * inv;
            }
        }
        // no trailing barrier: wred(i+1) writes happen only after bar1(i+1),
        // and s_inv(i) was consumed into a register after bar2(i).
    }

    // flush: vector-RED into one of 8 replica arrays (16B-aligned rows),
    // fire-and-forget (kernel boundary provides global visibility for k_fin).
    float* rep = g_rep[bid & (NREP - 1)];
    #pragma unroll
    for (int k = 0; k < 3; k++) {
        int idx = tid + 1024 * k;
        if (k < 2 || idx < C4) {
            float* p = rep + 4 * idx;
            asm volatile("red.global.add.v4.f32 [%0], {%1, %2, %3, %4};"
                         :: "l"(p), "f"(acc[k][0]), "f"(acc[k][1]),
                            "f"(acc[k][2]), "f"(acc[k][3]) : "memory");
        }
    }
}

// ---------------------------------------------------------------- tiny epilogue
// 40 blocks x 256 threads: <=1 class per thread. Read 8 L2-hot replicas +
// count, |conf - count|/B, consume-and-clear state for the next replay,
// block-reduce, one atomicAdd per block.
__global__ __launch_bounds__(256) void k_fin(float* __restrict__ out) {
    const int tid = threadIdx.x;
    const int c   = blockIdx.x * 256 + tid;

    float s = 0.0f;
    if (c < CLASSES) {
        float v = 0.0f;
        #pragma unroll
        for (int p = 0; p < NREP; p++) { v += g_rep[p][c]; g_rep[p][c] = 0.0f; }
        v -= g_counts[c];
        g_counts[c] = 0.0f;                  // clear for next replay
        s = fabsf(v) * (1.0f / (float)BATCH);
    }

    __shared__ float sm[8];
    #pragma unroll
    for (int o = 16; o; o >>= 1) s += __shfl_down_sync(0xffffffffu, s, o);
    if ((tid & 31) == 0) sm[tid >> 5] = s;
    __syncthreads();
    if (tid < 8) {
        float t = sm[tid];
        t += __shfl_down_sync(0xffu, t, 4);
        t += __shfl_down_sync(0xffu, t, 2);
        t += __shfl_down_sync(0xffu, t, 1);
        if (tid == 0) atomicAdd(out, t / (float)CLASSES);
    }
}

// ---------------------------------------------------------------- launch
extern "C" void kernel_launch(void* const* d_in, const int* in_sizes, int n_in,
                              void* d_out, int out_size) {
    const float* x   = (const float*)d_in[0];   // [8192, 10000] fp32
    const int*   tgt = (const int*)d_in[1];     // [8192] int32 or int64 (detected)
    float*       out = (float*)d_out;

    int sms = 0;
    cudaDeviceGetAttribute(&sms, cudaDevAttrMultiProcessorCount, 0);
    int grid = sms;                              // 1 persistent CTA per SM
    if (grid < 9)       grid = 9;                // histogram needs blocks 0..7
    if (grid > MAXGRID) grid = MAXGRID;

    cudaFuncSetAttribute(k_main, cudaFuncAttributeMaxDynamicSharedMemorySize,
                         SMEM_DYN);

    k_main<<<grid, THREADS, SMEM_DYN>>>(x, tgt, out, grid);
    k_fin<<<(CLASSES + 255) / 256, 256>>>(out);   // 40 blocks
}

// round 17
// speedup vs baseline: 1.5708x; 1.1856x over previous
#include <cuda_runtime.h>
#include <cstdint>

#define BATCH   8192
#define CLASSES 10000
#define C4      2500                    // float4 per row
#define TROWS   2                       // rows per tile
#define NTILES  (BATCH / TROWS)         // 4096
#define THREADS 1024
#define MAXGRID 160
#define NREP    8
#define NBUF    2
#define ROW_BYTES  (CLASSES * 4)        // 40000
#define TILE_BYTES (TROWS * ROW_BYTES)  // 80000
#define CHUNK      10000                // 8 bulk copies per tile -> 16 in flight
#define SMEM_DYN   (NBUF * TILE_BYTES)  // 160000 B raw ring

// zero-initialized at module load; k_fin consume-and-clears after each use,
// so the invariant "zeroed at kernel_launch entry" holds on every replay.
__device__ float g_rep[NREP][CLASSES];
__device__ float g_counts[CLASSES];

// ---------------------------------------------------------------- helpers
__device__ __forceinline__ uint32_t s2u(const void* p) {
    uint32_t a;
    asm("{ .reg .u64 t; cvta.to.shared.u64 t, %1; cvt.u32.u64 %0, t; }"
        : "=r"(a) : "l"(p));
    return a;
}

__device__ __forceinline__ void mbar_init(uint32_t mb, uint32_t cnt) {
    asm volatile("mbarrier.init.shared.b64 [%0], %1;" :: "r"(mb), "r"(cnt) : "memory");
}

__device__ __forceinline__ void mbar_wait(uint32_t mb, uint32_t parity) {
    asm volatile(
        "{\n\t"
        ".reg .pred P;\n\t"
        "WL_%=: mbarrier.try_wait.parity.acquire.cta.shared::cta.b64 P, [%0], %1, 0x989680;\n\t"
        "@P bra.uni WD_%=;\n\t"
        "bra.uni WL_%=;\n\t"
        "WD_%=:\n\t"
        "}" :: "r"(mb), "r"(parity) : "memory");
}

// one elected thread: expect_tx + EIGHT bulk-async 10000B copies (one 2-row
// tile). Per-UBLKCP service rate is bounded (R15 vs R16: 1 vs 4 copies/tile
// = 83 vs 61.5us), so keep >=16 copies in flight across the 2 buffers.
__device__ __forceinline__ void issue_tile(const float* __restrict__ x,
                                           char* dyn, uint32_t mb,
                                           int buf, long long tile) {
    asm volatile("mbarrier.arrive.expect_tx.shared.b64 _, [%0], %1;"
                 :: "r"(mb), "r"((uint32_t)TILE_BYTES) : "memory");
    const char* src = (const char*)x + (size_t)tile * TILE_BYTES;
    uint32_t dst = s2u(dyn + buf * TILE_BYTES);
    #pragma unroll
    for (int c = 0; c < 8; c++) {
        asm volatile(
            "cp.async.bulk.shared::cta.global.mbarrier::complete_tx::bytes "
            "[%0], [%1], %2, [%3];"
            :: "r"(dst + c * CHUNK), "l"(src + (size_t)c * CHUNK),
               "r"((uint32_t)CHUNK), "r"(mb) : "memory");
    }
}

// ---------------------------------------------------------------- persistent main
// 1 CTA/SM, 1024 threads, 2-deep ring of 2-row tiles (27 iterations/CTA ==
// R14's barrier overhead) fed by 8-way-split bulk copies (R16's copy
// concurrency). Thread t owns float4 class-groups {t, t+1024, t+2048} of
// BOTH rows: exps live in 24 registers, two row sums reduced in parallel by
// warps 0/1, accumulate straight from registers. No fp16 stage, full fp32,
// 2 barriers per tile. Histogram in blocks 0..7 overlapped with the
// mainloop. Flush = red.global.add.v4 into one of 8 replica arrays.
__global__ __launch_bounds__(THREADS, 1) void k_main(const float* __restrict__ x,
                                                     const int* __restrict__ tgt,
                                                     float* __restrict__ out,
                                                     int grid) {
    extern __shared__ char dyn[];
    __shared__ float    wred0[32], wred1[32];
    __shared__ float    s_inv0, s_inv1;
    __shared__ uint64_t mbar[NBUF];

    const int tid = threadIdx.x;
    const int bid = blockIdx.x;
    if (bid == 0 && tid == 0) out[0] = 0.0f;   // ordered before k_fin (stream)

    const uint32_t mb0 = s2u(&mbar[0]);
    const uint32_t mb1 = s2u(&mbar[1]);
    if (tid == 0) { mbar_init(mb0, 1); mbar_init(mb1, 1); }
    __syncthreads();

    const int n = (NTILES - 1 - bid) / grid + 1;   // tiles owned by this CTA
    if (tid == 0) {
        issue_tile(x, dyn, mb0, 0, bid);
        if (n > 1) issue_tile(x, dyn, mb1, 1, bid + (long long)grid);
    }

    // histogram side-job (blocks 0..7, 1024 targets each), overlapped with
    // the TMA-fed mainloop. Dtype-robust: detect int64-LE (odd int32 words
    // zero for values < 2^32) vs int32.
    if (bid < 8) {
        bool is64 = true;
        #pragma unroll
        for (int j = 1; j < 16; j += 2) is64 = is64 && (tgt[j] == 0);
        int i = bid * 1024 + tid;
        int t = is64 ? tgt[2 * i] : tgt[i];
        if (t >= 0 && t < CLASSES) atomicAdd(&g_counts[t], 1.0f);
    }

    float acc[3][4];
    #pragma unroll
    for (int k = 0; k < 3; k++)
        acc[k][0] = acc[k][1] = acc[k][2] = acc[k][3] = 0.0f;

    int ph0 = 0, ph1 = 0;

    for (int i = 0; i < n; i++) {
        const int buf = i & 1;
        const uint32_t mb = buf ? mb1 : mb0;
        mbar_wait(mb, buf ? ph1 : ph0);
        if (buf) ph1 ^= 1; else ph0 ^= 1;

        const float4* rowA = reinterpret_cast<const float4*>(dyn + buf * TILE_BYTES);
        const float4* rowB = rowA + C4;

        // ---- exp + two row sums, exps kept in registers (24 regs)
        float eA[3][4], eB[3][4];
        float sA = 0.0f, sB = 0.0f;
        #pragma unroll
        for (int k = 0; k < 3; k++) {
            int idx = tid + 1024 * k;
            if (k < 2 || idx < C4) {
                float4 va = rowA[idx];
                float4 vb = rowB[idx];
                eA[k][0] = __expf(va.x); eA[k][1] = __expf(va.y);
                eA[k][2] = __expf(va.z); eA[k][3] = __expf(va.w);
                eB[k][0] = __expf(vb.x); eB[k][1] = __expf(vb.y);
                eB[k][2] = __expf(vb.z); eB[k][3] = __expf(vb.w);
                sA += (eA[k][0] + eA[k][1]) + (eA[k][2] + eA[k][3]);
                sB += (eB[k][0] + eB[k][1]) + (eB[k][2] + eB[k][3]);
            }
        }
        #pragma unroll
        for (int o = 16; o; o >>= 1) {
            sA += __shfl_down_sync(0xffffffffu, sA, o);
            sB += __shfl_down_sync(0xffffffffu, sB, o);
        }
        if ((tid & 31) == 0) { wred0[tid >> 5] = sA; wred1[tid >> 5] = sB; }
        __syncthreads();                     // raw reads + wred stores done

        // re-arm this buffer for tile i+2 while everyone else proceeds
        if (tid == 0 && i + 2 < n)
            issue_tile(x, dyn, mb, buf, bid + (long long)(i + 2) * grid);

        if (tid < 32) {                      // warp 0 reduces row A
            float t = wred0[tid];
            #pragma unroll
            for (int o = 16; o; o >>= 1) t += __shfl_down_sync(0xffffffffu, t, o);
            if (tid == 0) s_inv0 = 1.0f / t;
        } else if (tid < 64) {               // warp 1 reduces row B
            float t = wred1[tid - 32];
            #pragma unroll
            for (int o = 16; o; o >>= 1) t += __shfl_down_sync(0xffffffffu, t, o);
            if (tid == 32) s_inv1 = 1.0f / t;
        }
        __syncthreads();
        const float invA = s_inv0, invB = s_inv1;

        // ---- accumulate: same thread<->class map, straight from registers
        #pragma unroll
        for (int k = 0; k < 3; k++) {
            int idx = tid + 1024 * k;
            if (k < 2 || idx < C4) {
                acc[k][0] += eA[k][0] * invA + eB[k][0] * invB;
                acc[k][1] += eA[k][1] * invA + eB[k][1] * invB;
                acc[k][2] += eA[k][2] * invA + eB[k][2] * invB;
                acc[k][3] += eA[k][3] * invA + eB[k][3] * invB;
            }
        }
        // no trailing barrier: wred(i+1) writes happen only after bar1(i+1);
        // s_inv was consumed into registers after bar2(i).
    }

    // flush: vector-RED into one of 8 replica arrays (16B-aligned rows),
    // fire-and-forget (kernel boundary provides global visibility for k_fin).
    float* rep = g_rep[bid & (NREP - 1)];
    #pragma unroll
    for (int k = 0; k < 3; k++) {
        int idx = tid + 1024 * k;
        if (k < 2 || idx < C4) {
            float* p = rep + 4 * idx;
            asm volatile("red.global.add.v4.f32 [%0], {%1, %2, %3, %4};"
                         :: "l"(p), "f"(acc[k][0]), "f"(acc[k][1]),
                            "f"(acc[k][2]), "f"(acc[k][3]) : "memory");
        }
    }
}

// ---------------------------------------------------------------- tiny epilogue
// 40 blocks x 256 threads: <=1 class per thread. Read 8 L2-hot replicas +
// count, |conf - count|/B, consume-and-clear state for the next replay,
// block-reduce, one atomicAdd per block.
__global__ __launch_bounds__(256) void k_fin(float* __restrict__ out) {
    const int tid = threadIdx.x;
    const int c   = blockIdx.x * 256 + tid;

    float s = 0.0f;
    if (c < CLASSES) {
        float v = 0.0f;
        #pragma unroll
        for (int p = 0; p < NREP; p++) { v += g_rep[p][c]; g_rep[p][c] = 0.0f; }
        v -= g_counts[c];
        g_counts[c] = 0.0f;                  // clear for next replay
        s = fabsf(v) * (1.0f / (float)BATCH);
    }

    __shared__ float sm[8];
    #pragma unroll
    for (int o = 16; o; o >>= 1) s += __shfl_down_sync(0xffffffffu, s, o);
    if ((tid & 31) == 0) sm[tid >> 5] = s;
    __syncthreads();
    if (tid < 8) {
        float t = sm[tid];
        t += __shfl_down_sync(0xffu, t, 4);
        t += __shfl_down_sync(0xffu, t, 2);
        t += __shfl_down_sync(0xffu, t, 1);
        if (tid == 0) atomicAdd(out, t / (float)CLASSES);
    }
}

// ---------------------------------------------------------------- launch
extern "C" void kernel_launch(void* const* d_in, const int* in_sizes, int n_in,
                              void* d_out, int out_size) {
    const float* x   = (const float*)d_in[0];   // [8192, 10000] fp32
    const int*   tgt = (const int*)d_in[1];     // [8192] int32 or int64 (detected)
    float*       out = (float*)d_out;

    int sms = 0;
    cudaDeviceGetAttribute(&sms, cudaDevAttrMultiProcessorCount, 0);
    int grid = sms;                              // 1 persistent CTA per SM
    if (grid < 9)       grid = 9;                // histogram needs blocks 0..7
    if (grid > MAXGRID) grid = MAXGRID;

    cudaFuncSetAttribute(k_main, cudaFuncAttributeMaxDynamicSharedMemorySize,
                         SMEM_DYN);

    k_main<<<grid, THREADS, SMEM_DYN>>>(x, tgt, out, grid);
    k_fin<<<(CLASSES + 255) / 256, 256>>>(out);   // 40 blocks
}